// round 4
// baseline (speedup 1.0000x reference)
#include <cuda_runtime.h>
#include <math.h>
#include <stdint.h>

#define R 1024
#define CIN 256
#define CHID 32
#define NH 8
#define CZ 128
#define HD 256   // NH*CHID
#define NSPLIT 8

// Scratch (static device globals — no runtime allocation)
__device__ float g_mn[R * CIN];
__device__ float g_q[R * HD];
__device__ float g_k[R * HD];
__device__ float g_v[R * HD];
__device__ float g_gw[R * HD];
__device__ float g_bias[(size_t)NH * R * R];   // 32 MB, layout [h][i][j]
__device__ float g_o[R * HD];
__device__ float g_pm[NSPLIT * NH * R];
__device__ float g_pl[NSPLIT * NH * R];
__device__ float g_po[(size_t)NSPLIT * NH * R * CHID];

// ---- packed f32x2 helpers (FFMA2 — only reachable via PTX) ----------------
__device__ __forceinline__ unsigned long long fma2(unsigned long long a,
                                                   unsigned long long b,
                                                   unsigned long long c) {
    unsigned long long d;
    asm("fma.rn.f32x2 %0, %1, %2, %3;" : "=l"(d) : "l"(a), "l"(b), "l"(c));
    return d;
}
__device__ __forceinline__ unsigned long long add2(unsigned long long a,
                                                   unsigned long long b) {
    unsigned long long d;
    asm("add.rn.f32x2 %0, %1, %2;" : "=l"(d) : "l"(a), "l"(b));
    return d;
}
__device__ __forceinline__ float2 unpk2(unsigned long long v) {
    float2 r;
    asm("mov.b64 {%0, %1}, %2;" : "=f"(r.x), "=f"(r.y) : "l"(v));
    return r;
}
__device__ __forceinline__ unsigned long long pk2(float a, float b) {
    unsigned long long d;
    asm("mov.b64 %0, {%1, %2};" : "=l"(d) : "f"(a), "f"(b));
    return d;
}
__device__ __forceinline__ void cpa16(uint32_t dst, const void* src) {
    asm volatile("cp.async.cg.shared.global [%0], [%1], 16;" :: "r"(dst), "l"(src));
}
__device__ __forceinline__ void cpa_commit() {
    asm volatile("cp.async.commit_group;" ::: "memory");
}
template <int N>
__device__ __forceinline__ void cpa_wait() {
    asm volatile("cp.async.wait_group %0;" :: "n"(N) : "memory");
}

// ---------------------------------------------------------------------------
// K1: mn = LayerNorm(m) * w + b
// ---------------------------------------------------------------------------
__global__ void k_lnm(const float* __restrict__ m,
                      const float* __restrict__ w,
                      const float* __restrict__ b) {
    int row = blockIdx.x;
    int c = threadIdx.x;
    float x = m[row * CIN + c];
    float s = x, ss = x * x;
    __shared__ float red[16];
    #pragma unroll
    for (int o = 16; o > 0; o >>= 1) {
        s  += __shfl_xor_sync(0xffffffffu, s, o);
        ss += __shfl_xor_sync(0xffffffffu, ss, o);
    }
    int lane = c & 31, wid = c >> 5;
    if (lane == 0) { red[wid] = s; red[wid + 8] = ss; }
    __syncthreads();
    if (c == 0) {
        float s2 = 0.f, ss2 = 0.f;
        #pragma unroll
        for (int i = 0; i < 8; i++) { s2 += red[i]; ss2 += red[i + 8]; }
        red[0] = s2; red[8] = ss2;
    }
    __syncthreads();
    float mu  = red[0] * (1.0f / CIN);
    float var = red[8] * (1.0f / CIN) - mu * mu;
    float rs  = rsqrtf(var + 1e-5f);
    g_mn[row * CIN + c] = (x - mu) * rs * w[c] + b[c];
}

// ---------------------------------------------------------------------------
// K2: Q,K,V,Gw = mn @ {Wq,Wk,Wv,Wg}
// ---------------------------------------------------------------------------
__global__ void k_qkvg(const float* __restrict__ Wq, const float* __restrict__ Wk,
                       const float* __restrict__ Wv, const float* __restrict__ Wg) {
    const float* W;
    float* out;
    float scale = 1.0f;
    int mz = blockIdx.z;
    if (mz == 0)      { W = Wq; out = g_q; scale = 0.17677669529663687f; }
    else if (mz == 1) { W = Wk; out = g_k; }
    else if (mz == 2) { W = Wv; out = g_v; }
    else              { W = Wg; out = g_gw; }

    int r0 = blockIdx.y * 64, c0 = blockIdx.x * 64;
    __shared__ float As[32][72];
    __shared__ float Bs[32][72];
    int tid = threadIdx.x;
    int tr = tid >> 4, tc = tid & 15;
    float acc[4][4] = {};

    for (int k0 = 0; k0 < CIN; k0 += 32) {
        #pragma unroll
        for (int t = 0; t < 8; t++) {
            int idx = tid + t * 256;
            int r = idx >> 5, kk = idx & 31;
            As[kk][r] = g_mn[(r0 + r) * CIN + k0 + kk];
        }
        #pragma unroll
        for (int t = 0; t < 8; t++) {
            int idx = tid + t * 256;
            int kk = idx >> 6, cc = idx & 63;
            Bs[kk][cc] = W[(k0 + kk) * HD + c0 + cc];
        }
        __syncthreads();
        #pragma unroll
        for (int kk = 0; kk < 32; kk++) {
            float4 a4 = *(const float4*)&As[kk][4 * tr];
            float4 b4 = *(const float4*)&Bs[kk][4 * tc];
            float av[4] = {a4.x, a4.y, a4.z, a4.w};
            float bv[4] = {b4.x, b4.y, b4.z, b4.w};
            #pragma unroll
            for (int rr = 0; rr < 4; rr++)
                #pragma unroll
                for (int cc = 0; cc < 4; cc++)
                    acc[rr][cc] += av[rr] * bv[cc];
        }
        __syncthreads();
    }
    #pragma unroll
    for (int rr = 0; rr < 4; rr++) {
        float4 o4 = make_float4(acc[rr][0] * scale, acc[rr][1] * scale,
                                acc[rr][2] * scale, acc[rr][3] * scale);
        *(float4*)&out[(r0 + 4 * tr + rr) * HD + c0 + 4 * tc] = o4;
    }
}

// ---------------------------------------------------------------------------
// K3 (v3): 4 lanes per row, 256 threads, cp.async double-buffered.
// Tile: 64 rows x 128 floats; smem row = 4 chunks of 32 words at 36-word
// stride (row stride 144 words) -> conflict-free LDS.128.
// Warp w handles rows w*8..w*8+7; lane quad (g=lane&3) splits the 128 cols.
// Weight table ws: 32 rows (u*4+g) x 16 ullongs (p0 heads0-7, p1 heads0-7),
// row stride 20 ullongs -> conflict-free broadcast loads.
// grid (2, 1024), 256 threads. ~81 KB smem -> 2 blocks/SM, 16 warps/SM.
// ---------------------------------------------------------------------------
#define BT_ROWS 64
#define BT_RS 144        // words per row in smem
#define BT_CHUNK 36      // words per g-chunk
#define BT_TILES 8
#define WS_STRIDE 20     // ullongs per ws row

__global__ __launch_bounds__(256) void k_bias(const float* __restrict__ z,
                                              const float* __restrict__ lnw,
                                              const float* __restrict__ lnb,
                                              const float* __restrict__ Wz) {
    __shared__ __align__(16) float zs[2][BT_ROWS * BT_RS];
    __shared__ __align__(16) unsigned long long ws[32 * WS_STRIDE];
    __shared__ float sb[NH * BT_ROWS];
    __shared__ float s_cs[NH], s_cb[NH];

    int tid = threadIdx.x;
    int i  = blockIdx.y;
    int jb = blockIdx.x * (BT_ROWS * BT_TILES);   // 512-j strip

    const float* zstrip = z + ((size_t)i * R + jb) * CZ;
    uint32_t zs_base[2];
    zs_base[0] = (uint32_t)__cvta_generic_to_shared(&zs[0][0]);
    zs_base[1] = (uint32_t)__cvta_generic_to_shared(&zs[1][0]);

    // ---- issue tile 0 immediately (8 x 16B per thread)
    {
        #pragma unroll
        for (int k = 0; k < 8; k++) {
            int idx = tid + k * 256;           // 0..2047
            int row = idx >> 5, s4 = idx & 31;
            uint32_t dw = (uint32_t)(row * BT_RS + (s4 >> 3) * BT_CHUNK + (s4 & 7) * 4);
            cpa16(zs_base[0] + dw * 4, zstrip + row * CZ + s4 * 4);
        }
        cpa_commit();
    }

    // ---- build weight table: row q = u*4+g; slots 0..7 = pair p0 heads,
    //      slots 8..15 = pair p1 heads;  p0 = 16g+2u, p1 = p0+1.
    {
        #pragma unroll
        for (int e = 0; e < 2; e++) {
            int f = tid * 2 + e;               // 0..511
            int rowq = f >> 4, slot = f & 15;
            int u = rowq >> 2, g = rowq & 3;
            int p = 16 * g + 2 * u + (slot >> 3);
            int h = slot & 7;
            int c = 2 * p;
            ws[rowq * WS_STRIDE + slot] =
                pk2(lnw[c] * Wz[c * NH + h], lnw[c + 1] * Wz[(c + 1) * NH + h]);
        }
    }
    if (tid < NH) {
        float cb = 0.f;
        #pragma unroll 4
        for (int c = 0; c < CZ; c++) cb += lnb[c] * Wz[c * NH + tid];
        s_cb[tid] = cb;
    }
    __syncthreads();
    if (tid < NH) {
        float cs = 0.f;
        #pragma unroll
        for (int q = 0; q < 32; q++) {
            float2 a = unpk2(ws[q * WS_STRIDE + tid]);
            float2 b = unpk2(ws[q * WS_STRIDE + 8 + tid]);
            cs += a.x + a.y + b.x + b.y;
        }
        s_cs[tid] = cs;
    }
    // (first in-loop __syncthreads orders s_cs/s_cb for all readers)

    int lane = tid & 31, w = tid >> 5;
    int rrow = w * 8 + (lane >> 2);   // row within tile
    int g = lane & 3;

    // ---- main loop over 8 tiles, double buffered
    for (int tt = 0; tt < BT_TILES; tt++) {
        if (tt + 1 < BT_TILES) {
            int nb = (tt + 1) & 1;
            const float* src = zstrip + (size_t)(tt + 1) * BT_ROWS * CZ;
            #pragma unroll
            for (int k = 0; k < 8; k++) {
                int idx = tid + k * 256;
                int row = idx >> 5, s4 = idx & 31;
                uint32_t dw = (uint32_t)(row * BT_RS + (s4 >> 3) * BT_CHUNK + (s4 & 7) * 4);
                cpa16(zs_base[nb] + dw * 4, src + row * CZ + s4 * 4);
            }
            cpa_commit();
            cpa_wait<1>();
        } else {
            cpa_wait<0>();
        }
        __syncthreads();

        // ---- compute: this thread covers els [32g, 32g+32) of row rrow
        const float* zr = &zs[tt & 1][rrow * BT_RS + g * BT_CHUNK];
        unsigned long long aD[NH] = {0ull,0ull,0ull,0ull,0ull,0ull,0ull,0ull};
        unsigned long long aS = 0ull, aQ = 0ull;

        #pragma unroll
        for (int u = 0; u < 8; u++) {
            ulonglong2 zz = *(const ulonglong2*)(zr + 4 * u);
            aS = add2(aS, add2(zz.x, zz.y));
            aQ = fma2(zz.x, zz.x, aQ);
            aQ = fma2(zz.y, zz.y, aQ);
            const ulonglong2* wp = (const ulonglong2*)&ws[(u * 4 + g) * WS_STRIDE];
            #pragma unroll
            for (int k = 0; k < 4; k++) {
                ulonglong2 wa = wp[k];       // p0, heads 2k,2k+1
                ulonglong2 wb = wp[4 + k];   // p1, heads 2k,2k+1
                aD[2 * k]     = fma2(zz.x, wa.x, aD[2 * k]);
                aD[2 * k + 1] = fma2(zz.x, wa.y, aD[2 * k + 1]);
                aD[2 * k]     = fma2(zz.y, wb.x, aD[2 * k]);
                aD[2 * k + 1] = fma2(zz.y, wb.y, aD[2 * k + 1]);
            }
        }

        // ---- quad reduction (xor 1,2 within each 4-lane group)
        float2 dS = unpk2(aS), dQ = unpk2(aQ);
        float s  = dS.x + dS.y;
        float qq = dQ.x + dQ.y;
        float dh[NH];
        #pragma unroll
        for (int h = 0; h < NH; h++) {
            float2 dd = unpk2(aD[h]);
            dh[h] = dd.x + dd.y;
        }
        #pragma unroll
        for (int o = 1; o <= 2; o <<= 1) {
            s  += __shfl_xor_sync(0xffffffffu, s, o);
            qq += __shfl_xor_sync(0xffffffffu, qq, o);
            #pragma unroll
            for (int h = 0; h < NH; h++)
                dh[h] += __shfl_xor_sync(0xffffffffu, dh[h], o);
        }

        if (g == 0) {
            float mu  = s * (1.0f / CZ);
            float var = qq * (1.0f / CZ) - mu * mu;
            float rs  = rsqrtf(var + 1e-5f);
            #pragma unroll
            for (int h = 0; h < NH; h++)
                sb[h * BT_ROWS + rrow] = rs * (dh[h] - mu * s_cs[h]) + s_cb[h];
        }
        __syncthreads();

        // ---- coalesced bias write (64-float contiguous segments per head)
        size_t jt0 = (size_t)jb + tt * BT_ROWS;
        #pragma unroll
        for (int k = 0; k < 2; k++) {
            int idx = tid + k * 256;
            int hh = idx >> 6, jj = idx & 63;
            g_bias[((size_t)hh * R + i) * R + jt0 + jj] = sb[hh * BT_ROWS + jj];
        }
        __syncthreads();   // sb + zs buffer safe for reuse
    }
}

// ---------------------------------------------------------------------------
// K4: flash attention with additive bias, SPLIT over j (NSPLIT=8).
// grid (16 q-tiles, 8 heads, 8 j-splits), 256 threads; 128 j per block.
// ---------------------------------------------------------------------------
__global__ void k_attn() {
    int h   = blockIdx.y;
    int q0  = blockIdx.x * 64;
    int zsp = blockIdx.z;
    int tid = threadIdx.x;
    int tr = tid >> 4, tc = tid & 15;

    __shared__ float qT[32][72];
    __shared__ float kT[32][72];
    __shared__ float vs[64][36];
    __shared__ float ps[64][68];
    __shared__ float m_s[64], l_s[64], f_s[64];

    #pragma unroll
    for (int t = 0; t < 8; t++) {
        int idx = tid + t * 256;
        int r = idx >> 5, d = idx & 31;
        qT[d][r] = g_q[(q0 + r) * HD + h * CHID + d];
    }
    if (tid < 64) { m_s[tid] = -1e30f; l_s[tid] = 0.f; }

    float o[4][2] = {};

    for (int jt = 0; jt < 2; jt++) {
        int j0 = zsp * 128 + jt * 64;
        __syncthreads();
        #pragma unroll
        for (int t = 0; t < 8; t++) {
            int idx = tid + t * 256;
            int r = idx >> 5, d = idx & 31;
            kT[d][r] = g_k[(j0 + r) * HD + h * CHID + d];
            vs[r][d] = g_v[(j0 + r) * HD + h * CHID + d];
        }
        __syncthreads();

        float s[4][4];
        #pragma unroll
        for (int rr = 0; rr < 4; rr++) {
            float4 b4 = *(const float4*)&g_bias[((size_t)h * R + q0 + 4 * tr + rr) * R + j0 + 4 * tc];
            s[rr][0] = b4.x; s[rr][1] = b4.y; s[rr][2] = b4.z; s[rr][3] = b4.w;
        }
        #pragma unroll
        for (int kk = 0; kk < 32; kk++) {
            float4 a4 = *(const float4*)&qT[kk][4 * tr];
            float4 b4 = *(const float4*)&kT[kk][4 * tc];
            float av[4] = {a4.x, a4.y, a4.z, a4.w};
            float bv[4] = {b4.x, b4.y, b4.z, b4.w};
            #pragma unroll
            for (int rr = 0; rr < 4; rr++)
                #pragma unroll
                for (int cc = 0; cc < 4; cc++)
                    s[rr][cc] += av[rr] * bv[cc];
        }
        #pragma unroll
        for (int rr = 0; rr < 4; rr++)
            *(float4*)&ps[4 * tr + rr][4 * tc] =
                make_float4(s[rr][0], s[rr][1], s[rr][2], s[rr][3]);
        __syncthreads();

        {
            int row = tid >> 2, p = tid & 3;
            float mo = m_s[row];
            float mc = -1e30f;
            #pragma unroll
            for (int c = 0; c < 16; c += 4) {
                float4 v = *(const float4*)&ps[row][p * 16 + c];
                mc = fmaxf(mc, fmaxf(fmaxf(v.x, v.y), fmaxf(v.z, v.w)));
            }
            mc = fmaxf(mc, __shfl_xor_sync(0xffffffffu, mc, 1));
            mc = fmaxf(mc, __shfl_xor_sync(0xffffffffu, mc, 2));
            float mn2 = fmaxf(mo, mc);
            float l = 0.f;
            #pragma unroll
            for (int c = 0; c < 16; c += 4) {
                float4 v = *(const float4*)&ps[row][p * 16 + c];
                v.x = __expf(v.x - mn2); v.y = __expf(v.y - mn2);
                v.z = __expf(v.z - mn2); v.w = __expf(v.w - mn2);
                *(float4*)&ps[row][p * 16 + c] = v;
                l += v.x + v.y + v.z + v.w;
            }
            l += __shfl_xor_sync(0xffffffffu, l, 1);
            l += __shfl_xor_sync(0xffffffffu, l, 2);
            if (p == 0) {
                float f = __expf(mo - mn2);
                f_s[row] = f;
                l_s[row] = l_s[row] * f + l;
                m_s[row] = mn2;
            }
        }
        __syncthreads();

        float fr[4];
        #pragma unroll
        for (int rr = 0; rr < 4; rr++) fr[rr] = f_s[4 * tr + rr];
        #pragma unroll
        for (int rr = 0; rr < 4; rr++) { o[rr][0] *= fr[rr]; o[rr][1] *= fr[rr]; }

        #pragma unroll
        for (int j = 0; j < 64; j += 4) {
            float4 pv[4];
            #pragma unroll
            for (int rr = 0; rr < 4; rr++)
                pv[rr] = *(const float4*)&ps[4 * tr + rr][j];
            float2 vv[4];
            #pragma unroll
            for (int e = 0; e < 4; e++)
                vv[e] = *(const float2*)&vs[j + e][2 * tc];
            #pragma unroll
            for (int rr = 0; rr < 4; rr++) {
                o[rr][0] += pv[rr].x * vv[0].x; o[rr][1] += pv[rr].x * vv[0].y;
                o[rr][0] += pv[rr].y * vv[1].x; o[rr][1] += pv[rr].y * vv[1].y;
                o[rr][0] += pv[rr].z * vv[2].x; o[rr][1] += pv[rr].z * vv[2].y;
                o[rr][0] += pv[rr].w * vv[3].x; o[rr][1] += pv[rr].w * vv[3].y;
            }
        }
    }

    int base = (zsp * NH + h) * R + q0;
    #pragma unroll
    for (int rr = 0; rr < 4; rr++) {
        g_po[(size_t)(base + 4 * tr + rr) * CHID + 2 * tc + 0] = o[rr][0];
        g_po[(size_t)(base + 4 * tr + rr) * CHID + 2 * tc + 1] = o[rr][1];
    }
    __syncthreads();
    if (tid < 64) {
        g_pm[base + tid] = m_s[tid];
        g_pl[base + tid] = l_s[tid];
    }
}

// ---------------------------------------------------------------------------
// K4b: merge split-j partials -> g_o
// ---------------------------------------------------------------------------
__global__ void k_merge() {
    int idx = blockIdx.x * 256 + threadIdx.x;      // over NH*R*CHID = 262144
    int d = idx & (CHID - 1);
    int q = (idx >> 5) & (R - 1);
    int h = idx >> 15;

    float mv[NSPLIT];
    float M = -1e30f;
    #pragma unroll
    for (int s2 = 0; s2 < NSPLIT; s2++) {
        mv[s2] = g_pm[(s2 * NH + h) * R + q];
        M = fmaxf(M, mv[s2]);
    }
    float L = 0.f, ov = 0.f;
    #pragma unroll
    for (int s2 = 0; s2 < NSPLIT; s2++) {
        float e = __expf(mv[s2] - M);
        L  += g_pl[(s2 * NH + h) * R + q] * e;
        ov += g_po[(size_t)((s2 * NH + h) * R + q) * CHID + d] * e;
    }
    g_o[q * HD + h * CHID + d] = ov / L;
}

// ---------------------------------------------------------------------------
// K5: out = (o * sigmoid(gw)) @ Wo + bo
// ---------------------------------------------------------------------------
__global__ void k_out(const float* __restrict__ Wo,
                      const float* __restrict__ bo,
                      float* __restrict__ out) {
    int r0 = blockIdx.y * 64, c0 = blockIdx.x * 64;
    __shared__ float As[32][72];
    __shared__ float Bs[32][72];
    int tid = threadIdx.x;
    int tr = tid >> 4, tc = tid & 15;
    float acc[4][4] = {};

    for (int k0 = 0; k0 < HD; k0 += 32) {
        #pragma unroll
        for (int t = 0; t < 8; t++) {
            int idx = tid + t * 256;
            int r = idx >> 5, kk = idx & 31;
            int gi = (r0 + r) * HD + k0 + kk;
            float gate = 1.0f / (1.0f + __expf(-g_gw[gi]));
            As[kk][r] = g_o[gi] * gate;
        }
        #pragma unroll
        for (int t = 0; t < 8; t++) {
            int idx = tid + t * 256;
            int kk = idx >> 6, cc = idx & 63;
            Bs[kk][cc] = Wo[(k0 + kk) * CIN + c0 + cc];
        }
        __syncthreads();
        #pragma unroll
        for (int kk = 0; kk < 32; kk++) {
            float4 a4 = *(const float4*)&As[kk][4 * tr];
            float4 b4 = *(const float4*)&Bs[kk][4 * tc];
            float av[4] = {a4.x, a4.y, a4.z, a4.w};
            float bv[4] = {b4.x, b4.y, b4.z, b4.w};
            #pragma unroll
            for (int rr = 0; rr < 4; rr++)
                #pragma unroll
                for (int cc = 0; cc < 4; cc++)
                    acc[rr][cc] += av[rr] * bv[cc];
        }
        __syncthreads();
    }
    #pragma unroll
    for (int rr = 0; rr < 4; rr++) {
        int c = c0 + 4 * tc;
        float4 o4 = make_float4(acc[rr][0] + bo[c + 0], acc[rr][1] + bo[c + 1],
                                acc[rr][2] + bo[c + 2], acc[rr][3] + bo[c + 3]);
        *(float4*)&out[(r0 + 4 * tr + rr) * CIN + c] = o4;
    }
}

// ---------------------------------------------------------------------------
extern "C" void kernel_launch(void* const* d_in, const int* in_sizes, int n_in,
                              void* d_out, int out_size) {
    const float* m      = (const float*)d_in[0];
    const float* z      = (const float*)d_in[1];
    const float* ln_m_w = (const float*)d_in[2];
    const float* ln_m_b = (const float*)d_in[3];
    const float* ln_z_w = (const float*)d_in[4];
    const float* ln_z_b = (const float*)d_in[5];
    const float* Wz     = (const float*)d_in[6];
    const float* Wq     = (const float*)d_in[7];
    const float* Wk     = (const float*)d_in[8];
    const float* Wv     = (const float*)d_in[9];
    const float* Wg     = (const float*)d_in[10];
    // d_in[11] = bg (unused by reference)
    const float* Wo     = (const float*)d_in[12];
    const float* bo     = (const float*)d_in[13];
    float* out = (float*)d_out;

    k_lnm<<<R, 256>>>(m, ln_m_w, ln_m_b);
    k_qkvg<<<dim3(4, 16, 4), 256>>>(Wq, Wk, Wv, Wg);
    k_bias<<<dim3(2, R), 256>>>(z, ln_z_w, ln_z_b, Wz);
    k_attn<<<dim3(16, NH, NSPLIT), 256>>>();
    k_merge<<<NH * R * CHID / 256, 256>>>();
    k_out<<<dim3(4, 16), 256>>>(Wo, bo, out);
}

// round 5
// speedup vs baseline: 1.2328x; 1.2328x over previous
#include <cuda_runtime.h>
#include <math.h>
#include <stdint.h>

#define R 1024
#define CIN 256
#define CHID 32
#define NH 8
#define CZ 128
#define HD 256   // NH*CHID
#define NSPLIT 8

// Scratch (static device globals — no runtime allocation)
__device__ float g_mn[R * CIN];
__device__ float g_q[R * HD];
__device__ float g_k[R * HD];
__device__ float g_v[R * HD];
__device__ float g_gw[R * HD];
__device__ float g_bias[(size_t)NH * R * R];   // 32 MB, layout [h][i][j]
__device__ float g_o[R * HD];
__device__ float g_pm[NSPLIT * NH * R];
__device__ float g_pl[NSPLIT * NH * R];
__device__ float g_po[(size_t)NSPLIT * NH * R * CHID];

// ---- packed f32x2 helpers (FFMA2 — only reachable via PTX) ----------------
__device__ __forceinline__ unsigned long long fma2(unsigned long long a,
                                                   unsigned long long b,
                                                   unsigned long long c) {
    unsigned long long d;
    asm("fma.rn.f32x2 %0, %1, %2, %3;" : "=l"(d) : "l"(a), "l"(b), "l"(c));
    return d;
}
__device__ __forceinline__ unsigned long long add2(unsigned long long a,
                                                   unsigned long long b) {
    unsigned long long d;
    asm("add.rn.f32x2 %0, %1, %2;" : "=l"(d) : "l"(a), "l"(b));
    return d;
}
__device__ __forceinline__ float2 unpk2(unsigned long long v) {
    float2 r;
    asm("mov.b64 {%0, %1}, %2;" : "=f"(r.x), "=f"(r.y) : "l"(v));
    return r;
}
__device__ __forceinline__ unsigned long long pk2(float a, float b) {
    unsigned long long d;
    asm("mov.b64 %0, {%1, %2};" : "=l"(d) : "f"(a), "f"(b));
    return d;
}
__device__ __forceinline__ void cpa16(uint32_t dst, const void* src) {
    asm volatile("cp.async.cg.shared.global [%0], [%1], 16;" :: "r"(dst), "l"(src));
}
__device__ __forceinline__ void cpa_commit() {
    asm volatile("cp.async.commit_group;" ::: "memory");
}
template <int N>
__device__ __forceinline__ void cpa_wait() {
    asm volatile("cp.async.wait_group %0;" :: "n"(N) : "memory");
}

// ---------------------------------------------------------------------------
// K1: mn = LayerNorm(m) * w + b
// ---------------------------------------------------------------------------
__global__ void k_lnm(const float* __restrict__ m,
                      const float* __restrict__ w,
                      const float* __restrict__ b) {
    int row = blockIdx.x;
    int c = threadIdx.x;
    float x = m[row * CIN + c];
    float s = x, ss = x * x;
    __shared__ float red[16];
    #pragma unroll
    for (int o = 16; o > 0; o >>= 1) {
        s  += __shfl_xor_sync(0xffffffffu, s, o);
        ss += __shfl_xor_sync(0xffffffffu, ss, o);
    }
    int lane = c & 31, wid = c >> 5;
    if (lane == 0) { red[wid] = s; red[wid + 8] = ss; }
    __syncthreads();
    if (c == 0) {
        float s2 = 0.f, ss2 = 0.f;
        #pragma unroll
        for (int i = 0; i < 8; i++) { s2 += red[i]; ss2 += red[i + 8]; }
        red[0] = s2; red[8] = ss2;
    }
    __syncthreads();
    float mu  = red[0] * (1.0f / CIN);
    float var = red[8] * (1.0f / CIN) - mu * mu;
    float rs  = rsqrtf(var + 1e-5f);
    g_mn[row * CIN + c] = (x - mu) * rs * w[c] + b[c];
}

// ---------------------------------------------------------------------------
// K2: Q,K,V,Gw = mn @ {Wq,Wk,Wv,Wg}
// ---------------------------------------------------------------------------
__global__ void k_qkvg(const float* __restrict__ Wq, const float* __restrict__ Wk,
                       const float* __restrict__ Wv, const float* __restrict__ Wg) {
    const float* W;
    float* out;
    float scale = 1.0f;
    int mz = blockIdx.z;
    if (mz == 0)      { W = Wq; out = g_q; scale = 0.17677669529663687f; }
    else if (mz == 1) { W = Wk; out = g_k; }
    else if (mz == 2) { W = Wv; out = g_v; }
    else              { W = Wg; out = g_gw; }

    int r0 = blockIdx.y * 64, c0 = blockIdx.x * 64;
    __shared__ float As[32][72];
    __shared__ float Bs[32][72];
    int tid = threadIdx.x;
    int tr = tid >> 4, tc = tid & 15;
    float acc[4][4] = {};

    for (int k0 = 0; k0 < CIN; k0 += 32) {
        #pragma unroll
        for (int t = 0; t < 8; t++) {
            int idx = tid + t * 256;
            int r = idx >> 5, kk = idx & 31;
            As[kk][r] = g_mn[(r0 + r) * CIN + k0 + kk];
        }
        #pragma unroll
        for (int t = 0; t < 8; t++) {
            int idx = tid + t * 256;
            int kk = idx >> 6, cc = idx & 63;
            Bs[kk][cc] = W[(k0 + kk) * HD + c0 + cc];
        }
        __syncthreads();
        #pragma unroll
        for (int kk = 0; kk < 32; kk++) {
            float4 a4 = *(const float4*)&As[kk][4 * tr];
            float4 b4 = *(const float4*)&Bs[kk][4 * tc];
            float av[4] = {a4.x, a4.y, a4.z, a4.w};
            float bv[4] = {b4.x, b4.y, b4.z, b4.w};
            #pragma unroll
            for (int rr = 0; rr < 4; rr++)
                #pragma unroll
                for (int cc = 0; cc < 4; cc++)
                    acc[rr][cc] += av[rr] * bv[cc];
        }
        __syncthreads();
    }
    #pragma unroll
    for (int rr = 0; rr < 4; rr++) {
        float4 o4 = make_float4(acc[rr][0] * scale, acc[rr][1] * scale,
                                acc[rr][2] * scale, acc[rr][3] * scale);
        *(float4*)&out[(r0 + 4 * tr + rr) * HD + c0 + 4 * tc] = o4;
    }
}

// ---------------------------------------------------------------------------
// K3 (v4): 64 threads, thread = (rg, g): 4 rows each, k-chunk [32g,32g+32).
// 8 weight LDS.128 per u-step serve 4 rows (4x less weight smem traffic).
// Tile 64 rows x 128 floats, row stride 148 words (4 chunks of 36 + pad):
// phase banks {4*148*rg + 36g} mod 32 = {0,4,...,28} -> conflict-free.
// Weight table ws: 32 rows x 16 ullongs at stride 20 (broadcast-safe).
// grid (2, 1024), 64 threads, ~81 KB smem -> 2 blocks/SM, no reg spill.
// ---------------------------------------------------------------------------
#define BT_ROWS 64
#define BT_RS 148        // words per row in smem
#define BT_CHUNK 36      // words per g-chunk
#define BT_TILES 8
#define WS_STRIDE 20     // ullongs per ws row

__global__ __launch_bounds__(64) void k_bias(const float* __restrict__ z,
                                             const float* __restrict__ lnw,
                                             const float* __restrict__ lnb,
                                             const float* __restrict__ Wz) {
    __shared__ __align__(16) float zs[2][BT_ROWS * BT_RS];
    __shared__ __align__(16) unsigned long long ws[32 * WS_STRIDE];
    __shared__ float s_cs[NH], s_cb[NH];

    int tid = threadIdx.x;
    int i  = blockIdx.y;
    int jb = blockIdx.x * (BT_ROWS * BT_TILES);   // 512-j strip

    const float* zstrip = z + ((size_t)i * R + jb) * CZ;
    uint32_t zs_base[2];
    zs_base[0] = (uint32_t)__cvta_generic_to_shared(&zs[0][0]);
    zs_base[1] = (uint32_t)__cvta_generic_to_shared(&zs[1][0]);

    // ---- issue tile 0 (32 x 16B per thread)
    {
        #pragma unroll
        for (int k = 0; k < 32; k++) {
            int idx = tid + k * 64;            // 0..2047
            int row = idx >> 5, s4 = idx & 31;
            uint32_t dw = (uint32_t)(row * BT_RS + (s4 >> 3) * BT_CHUNK + (s4 & 7) * 4);
            cpa16(zs_base[0] + dw * 4, zstrip + row * CZ + s4 * 4);
        }
        cpa_commit();
    }

    // ---- build weight table: row q = u*4+g; slots 0..7 = pair p0 heads,
    //      slots 8..15 = pair p1 heads;  p0 = 16g+2u, p1 = p0+1.
    {
        #pragma unroll
        for (int e = 0; e < 8; e++) {
            int f = tid + e * 64;              // 0..511
            int rowq = f >> 4, slot = f & 15;
            int u = rowq >> 2, g = rowq & 3;
            int p = 16 * g + 2 * u + (slot >> 3);
            int h = slot & 7;
            int c = 2 * p;
            ws[rowq * WS_STRIDE + slot] =
                pk2(lnw[c] * Wz[c * NH + h], lnw[c + 1] * Wz[(c + 1) * NH + h]);
        }
    }
    if (tid < NH) {
        float cb = 0.f;
        #pragma unroll 4
        for (int c = 0; c < CZ; c++) cb += lnb[c] * Wz[c * NH + tid];
        s_cb[tid] = cb;
    }
    __syncthreads();
    if (tid < NH) {
        float cs = 0.f;
        #pragma unroll
        for (int q = 0; q < 32; q++) {
            float2 a = unpk2(ws[q * WS_STRIDE + tid]);
            float2 b = unpk2(ws[q * WS_STRIDE + 8 + tid]);
            cs += a.x + a.y + b.x + b.y;
        }
        s_cs[tid] = cs;
    }
    // (first in-loop __syncthreads orders s_cs/s_cb for all readers)

    int rg = tid >> 2;          // row group 0..15 (rows 4rg..4rg+3)
    int g  = tid & 3;           // k-chunk [32g, 32g+32)

    // ---- main loop over 8 tiles, double buffered
    for (int tt = 0; tt < BT_TILES; tt++) {
        if (tt + 1 < BT_TILES) {
            int nb = (tt + 1) & 1;
            const float* src = zstrip + (size_t)(tt + 1) * BT_ROWS * CZ;
            #pragma unroll
            for (int k = 0; k < 32; k++) {
                int idx = tid + k * 64;
                int row = idx >> 5, s4 = idx & 31;
                uint32_t dw = (uint32_t)(row * BT_RS + (s4 >> 3) * BT_CHUNK + (s4 & 7) * 4);
                cpa16(zs_base[nb] + dw * 4, src + row * CZ + s4 * 4);
            }
            cpa_commit();
            cpa_wait<1>();
        } else {
            cpa_wait<0>();
        }
        __syncthreads();

        // ---- compute: 4 rows, this thread's k-chunk
        const float* zb = &zs[tt & 1][(4 * rg) * BT_RS + g * BT_CHUNK];
        unsigned long long aD[4][NH];
        unsigned long long aS[4], aQ[4];
        #pragma unroll
        for (int r = 0; r < 4; r++) {
            aS[r] = 0ull; aQ[r] = 0ull;
            #pragma unroll
            for (int h = 0; h < NH; h++) aD[r][h] = 0ull;
        }

        #pragma unroll
        for (int u = 0; u < 8; u++) {
            const ulonglong2* wp = (const ulonglong2*)&ws[(u * 4 + g) * WS_STRIDE];
            ulonglong2 wa0 = wp[0], wa1 = wp[1], wa2 = wp[2], wa3 = wp[3];
            ulonglong2 wb0 = wp[4], wb1 = wp[5], wb2 = wp[6], wb3 = wp[7];
            #pragma unroll
            for (int r = 0; r < 4; r++) {
                ulonglong2 zz = *(const ulonglong2*)(zb + r * BT_RS + 4 * u);
                aS[r] = add2(aS[r], add2(zz.x, zz.y));
                aQ[r] = fma2(zz.x, zz.x, aQ[r]);
                aQ[r] = fma2(zz.y, zz.y, aQ[r]);
                aD[r][0] = fma2(zz.x, wa0.x, aD[r][0]);
                aD[r][1] = fma2(zz.x, wa0.y, aD[r][1]);
                aD[r][0] = fma2(zz.y, wb0.x, aD[r][0]);
                aD[r][1] = fma2(zz.y, wb0.y, aD[r][1]);
                aD[r][2] = fma2(zz.x, wa1.x, aD[r][2]);
                aD[r][3] = fma2(zz.x, wa1.y, aD[r][3]);
                aD[r][2] = fma2(zz.y, wb1.x, aD[r][2]);
                aD[r][3] = fma2(zz.y, wb1.y, aD[r][3]);
                aD[r][4] = fma2(zz.x, wa2.x, aD[r][4]);
                aD[r][5] = fma2(zz.x, wa2.y, aD[r][5]);
                aD[r][4] = fma2(zz.y, wb2.x, aD[r][4]);
                aD[r][5] = fma2(zz.y, wb2.y, aD[r][5]);
                aD[r][6] = fma2(zz.x, wa3.x, aD[r][6]);
                aD[r][7] = fma2(zz.x, wa3.y, aD[r][7]);
                aD[r][6] = fma2(zz.y, wb3.x, aD[r][6]);
                aD[r][7] = fma2(zz.y, wb3.y, aD[r][7]);
            }
        }

        // ---- unpack partials, quad-reduce (xor 1,2), write 2 heads per lane
        size_t jt0 = (size_t)jb + tt * BT_ROWS + 4 * rg;
        #pragma unroll
        for (int r = 0; r < 4; r++) {
            float2 dS = unpk2(aS[r]), dQ = unpk2(aQ[r]);
            float s  = dS.x + dS.y;
            float qq = dQ.x + dQ.y;
            float dh[NH];
            #pragma unroll
            for (int h = 0; h < NH; h++) {
                float2 dd = unpk2(aD[r][h]);
                dh[h] = dd.x + dd.y;
            }
            #pragma unroll
            for (int o = 1; o <= 2; o <<= 1) {
                s  += __shfl_xor_sync(0xffffffffu, s, o);
                qq += __shfl_xor_sync(0xffffffffu, qq, o);
                #pragma unroll
                for (int h = 0; h < NH; h++)
                    dh[h] += __shfl_xor_sync(0xffffffffu, dh[h], o);
            }
            float mu  = s * (1.0f / CZ);
            float var = qq * (1.0f / CZ) - mu * mu;
            float rs  = rsqrtf(var + 1e-5f);
            // stash per-row bias for this lane's two heads into registers
            int h0 = 2 * g, h1 = 2 * g + 1;
            aS[r] = pk2(rs * (dh[h0] - mu * s_cs[h0]) + s_cb[h0],
                        rs * (dh[h1] - mu * s_cs[h1]) + s_cb[h1]);
        }
        // aS[r] now = (bias_h0, bias_h1) for row r — build float4 over rows
        {
            int h0 = 2 * g, h1 = 2 * g + 1;
            float2 b0 = unpk2(aS[0]), b1 = unpk2(aS[1]);
            float2 b2 = unpk2(aS[2]), b3 = unpk2(aS[3]);
            *(float4*)&g_bias[((size_t)h0 * R + i) * R + jt0] =
                make_float4(b0.x, b1.x, b2.x, b3.x);
            *(float4*)&g_bias[((size_t)h1 * R + i) * R + jt0] =
                make_float4(b0.y, b1.y, b2.y, b3.y);
        }
        __syncthreads();   // zs buffer safe for reuse by next issue
    }
}

// ---------------------------------------------------------------------------
// K4: flash attention with additive bias, SPLIT over j (NSPLIT=8).
// grid (16 q-tiles, 8 heads, 8 j-splits), 256 threads; 128 j per block.
// ---------------------------------------------------------------------------
__global__ void k_attn() {
    int h   = blockIdx.y;
    int q0  = blockIdx.x * 64;
    int zsp = blockIdx.z;
    int tid = threadIdx.x;
    int tr = tid >> 4, tc = tid & 15;

    __shared__ float qT[32][72];
    __shared__ float kT[32][72];
    __shared__ float vs[64][36];
    __shared__ float ps[64][68];
    __shared__ float m_s[64], l_s[64], f_s[64];

    #pragma unroll
    for (int t = 0; t < 8; t++) {
        int idx = tid + t * 256;
        int r = idx >> 5, d = idx & 31;
        qT[d][r] = g_q[(q0 + r) * HD + h * CHID + d];
    }
    if (tid < 64) { m_s[tid] = -1e30f; l_s[tid] = 0.f; }

    float o[4][2] = {};

    for (int jt = 0; jt < 2; jt++) {
        int j0 = zsp * 128 + jt * 64;
        __syncthreads();
        #pragma unroll
        for (int t = 0; t < 8; t++) {
            int idx = tid + t * 256;
            int r = idx >> 5, d = idx & 31;
            kT[d][r] = g_k[(j0 + r) * HD + h * CHID + d];
            vs[r][d] = g_v[(j0 + r) * HD + h * CHID + d];
        }
        __syncthreads();

        float s[4][4];
        #pragma unroll
        for (int rr = 0; rr < 4; rr++) {
            float4 b4 = *(const float4*)&g_bias[((size_t)h * R + q0 + 4 * tr + rr) * R + j0 + 4 * tc];
            s[rr][0] = b4.x; s[rr][1] = b4.y; s[rr][2] = b4.z; s[rr][3] = b4.w;
        }
        #pragma unroll
        for (int kk = 0; kk < 32; kk++) {
            float4 a4 = *(const float4*)&qT[kk][4 * tr];
            float4 b4 = *(const float4*)&kT[kk][4 * tc];
            float av[4] = {a4.x, a4.y, a4.z, a4.w};
            float bv[4] = {b4.x, b4.y, b4.z, b4.w};
            #pragma unroll
            for (int rr = 0; rr < 4; rr++)
                #pragma unroll
                for (int cc = 0; cc < 4; cc++)
                    s[rr][cc] += av[rr] * bv[cc];
        }
        #pragma unroll
        for (int rr = 0; rr < 4; rr++)
            *(float4*)&ps[4 * tr + rr][4 * tc] =
                make_float4(s[rr][0], s[rr][1], s[rr][2], s[rr][3]);
        __syncthreads();

        {
            int row = tid >> 2, p = tid & 3;
            float mo = m_s[row];
            float mc = -1e30f;
            #pragma unroll
            for (int c = 0; c < 16; c += 4) {
                float4 v = *(const float4*)&ps[row][p * 16 + c];
                mc = fmaxf(mc, fmaxf(fmaxf(v.x, v.y), fmaxf(v.z, v.w)));
            }
            mc = fmaxf(mc, __shfl_xor_sync(0xffffffffu, mc, 1));
            mc = fmaxf(mc, __shfl_xor_sync(0xffffffffu, mc, 2));
            float mn2 = fmaxf(mo, mc);
            float l = 0.f;
            #pragma unroll
            for (int c = 0; c < 16; c += 4) {
                float4 v = *(const float4*)&ps[row][p * 16 + c];
                v.x = __expf(v.x - mn2); v.y = __expf(v.y - mn2);
                v.z = __expf(v.z - mn2); v.w = __expf(v.w - mn2);
                *(float4*)&ps[row][p * 16 + c] = v;
                l += v.x + v.y + v.z + v.w;
            }
            l += __shfl_xor_sync(0xffffffffu, l, 1);
            l += __shfl_xor_sync(0xffffffffu, l, 2);
            if (p == 0) {
                float f = __expf(mo - mn2);
                f_s[row] = f;
                l_s[row] = l_s[row] * f + l;
                m_s[row] = mn2;
            }
        }
        __syncthreads();

        float fr[4];
        #pragma unroll
        for (int rr = 0; rr < 4; rr++) fr[rr] = f_s[4 * tr + rr];
        #pragma unroll
        for (int rr = 0; rr < 4; rr++) { o[rr][0] *= fr[rr]; o[rr][1] *= fr[rr]; }

        #pragma unroll
        for (int j = 0; j < 64; j += 4) {
            float4 pv[4];
            #pragma unroll
            for (int rr = 0; rr < 4; rr++)
                pv[rr] = *(const float4*)&ps[4 * tr + rr][j];
            float2 vv[4];
            #pragma unroll
            for (int e = 0; e < 4; e++)
                vv[e] = *(const float2*)&vs[j + e][2 * tc];
            #pragma unroll
            for (int rr = 0; rr < 4; rr++) {
                o[rr][0] += pv[rr].x * vv[0].x; o[rr][1] += pv[rr].x * vv[0].y;
                o[rr][0] += pv[rr].y * vv[1].x; o[rr][1] += pv[rr].y * vv[1].y;
                o[rr][0] += pv[rr].z * vv[2].x; o[rr][1] += pv[rr].z * vv[2].y;
                o[rr][0] += pv[rr].w * vv[3].x; o[rr][1] += pv[rr].w * vv[3].y;
            }
        }
    }

    int base = (zsp * NH + h) * R + q0;
    #pragma unroll
    for (int rr = 0; rr < 4; rr++) {
        g_po[(size_t)(base + 4 * tr + rr) * CHID + 2 * tc + 0] = o[rr][0];
        g_po[(size_t)(base + 4 * tr + rr) * CHID + 2 * tc + 1] = o[rr][1];
    }
    __syncthreads();
    if (tid < 64) {
        g_pm[base + tid] = m_s[tid];
        g_pl[base + tid] = l_s[tid];
    }
}

// ---------------------------------------------------------------------------
// K4b: merge split-j partials -> g_o
// ---------------------------------------------------------------------------
__global__ void k_merge() {
    int idx = blockIdx.x * 256 + threadIdx.x;      // over NH*R*CHID = 262144
    int d = idx & (CHID - 1);
    int q = (idx >> 5) & (R - 1);
    int h = idx >> 15;

    float mv[NSPLIT];
    float M = -1e30f;
    #pragma unroll
    for (int s2 = 0; s2 < NSPLIT; s2++) {
        mv[s2] = g_pm[(s2 * NH + h) * R + q];
        M = fmaxf(M, mv[s2]);
    }
    float L = 0.f, ov = 0.f;
    #pragma unroll
    for (int s2 = 0; s2 < NSPLIT; s2++) {
        float e = __expf(mv[s2] - M);
        L  += g_pl[(s2 * NH + h) * R + q] * e;
        ov += g_po[(size_t)((s2 * NH + h) * R + q) * CHID + d] * e;
    }
    g_o[q * HD + h * CHID + d] = ov / L;
}

// ---------------------------------------------------------------------------
// K5: out = (o * sigmoid(gw)) @ Wo + bo
// ---------------------------------------------------------------------------
__global__ void k_out(const float* __restrict__ Wo,
                      const float* __restrict__ bo,
                      float* __restrict__ out) {
    int r0 = blockIdx.y * 64, c0 = blockIdx.x * 64;
    __shared__ float As[32][72];
    __shared__ float Bs[32][72];
    int tid = threadIdx.x;
    int tr = tid >> 4, tc = tid & 15;
    float acc[4][4] = {};

    for (int k0 = 0; k0 < HD; k0 += 32) {
        #pragma unroll
        for (int t = 0; t < 8; t++) {
            int idx = tid + t * 256;
            int r = idx >> 5, kk = idx & 31;
            int gi = (r0 + r) * HD + k0 + kk;
            float gate = 1.0f / (1.0f + __expf(-g_gw[gi]));
            As[kk][r] = g_o[gi] * gate;
        }
        #pragma unroll
        for (int t = 0; t < 8; t++) {
            int idx = tid + t * 256;
            int kk = idx >> 6, cc = idx & 63;
            Bs[kk][cc] = Wo[(k0 + kk) * CIN + c0 + cc];
        }
        __syncthreads();
        #pragma unroll
        for (int kk = 0; kk < 32; kk++) {
            float4 a4 = *(const float4*)&As[kk][4 * tr];
            float4 b4 = *(const float4*)&Bs[kk][4 * tc];
            float av[4] = {a4.x, a4.y, a4.z, a4.w};
            float bv[4] = {b4.x, b4.y, b4.z, b4.w};
            #pragma unroll
            for (int rr = 0; rr < 4; rr++)
                #pragma unroll
                for (int cc = 0; cc < 4; cc++)
                    acc[rr][cc] += av[rr] * bv[cc];
        }
        __syncthreads();
    }
    #pragma unroll
    for (int rr = 0; rr < 4; rr++) {
        int c = c0 + 4 * tc;
        float4 o4 = make_float4(acc[rr][0] + bo[c + 0], acc[rr][1] + bo[c + 1],
                                acc[rr][2] + bo[c + 2], acc[rr][3] + bo[c + 3]);
        *(float4*)&out[(r0 + 4 * tr + rr) * CIN + c] = o4;
    }
}

// ---------------------------------------------------------------------------
extern "C" void kernel_launch(void* const* d_in, const int* in_sizes, int n_in,
                              void* d_out, int out_size) {
    const float* m      = (const float*)d_in[0];
    const float* z      = (const float*)d_in[1];
    const float* ln_m_w = (const float*)d_in[2];
    const float* ln_m_b = (const float*)d_in[3];
    const float* ln_z_w = (const float*)d_in[4];
    const float* ln_z_b = (const float*)d_in[5];
    const float* Wz     = (const float*)d_in[6];
    const float* Wq     = (const float*)d_in[7];
    const float* Wk     = (const float*)d_in[8];
    const float* Wv     = (const float*)d_in[9];
    const float* Wg     = (const float*)d_in[10];
    // d_in[11] = bg (unused by reference)
    const float* Wo     = (const float*)d_in[12];
    const float* bo     = (const float*)d_in[13];
    float* out = (float*)d_out;

    k_lnm<<<R, 256>>>(m, ln_m_w, ln_m_b);
    k_qkvg<<<dim3(4, 16, 4), 256>>>(Wq, Wk, Wv, Wg);
    k_bias<<<dim3(2, R), 64>>>(z, ln_z_w, ln_z_b, Wz);
    k_attn<<<dim3(16, NH, NSPLIT), 256>>>();
    k_merge<<<NH * R * CHID / 256, 256>>>();
    k_out<<<dim3(4, 16), 256>>>(Wo, bo, out);
}